// round 2
// baseline (speedup 1.0000x reference)
#include <cuda_runtime.h>
#include <math_constants.h>

#define Dk 2048
#define Bk 32
#define LOG2E 1.4426950408889634f

// Scratch (no allocations allowed) -------------------------------------------
__device__ float  g_q2[Bk * Dk];   // q * log2(e)
__device__ float  g_k [Bk * Dk];
__device__ float  g_v [Bk * Dk];
__device__ float4 g_kmc[Bk * Dk];  // {k_j, -m2_j, v_j/S_j, 0}

__device__ __forceinline__ float ex2f(float x) {
    float r; asm("ex2.approx.f32 %0, %1;" : "=f"(r) : "f"(x)); return r;
}

// ---------------------------------------------------------------------------
// K1: fused projections  q2/k/v[b][col] = (x[b,:] . W[col,:]) + bias, q scaled
// Block: 128 thr (4 warps), 16 columns per block, warp = 4 cols, lane = batch.
// Row pad 260 floats (1040B ≡ 16 mod 128) -> conflict-free LDS.128 on x rows.
// ---------------------------------------------------------------------------
#define K1_COLS 16
#define ROWPAD  260
#define K1_SMEM ((32 * ROWPAD + K1_COLS * ROWPAD) * 4)   // 49920 B (dynamic)

__global__ __launch_bounds__(128, 1) void proj_kernel(
    const float* __restrict__ x,
    const float* __restrict__ Wq, const float* __restrict__ bq,
    const float* __restrict__ Wk, const float* __restrict__ bk,
    const float* __restrict__ Wv, const float* __restrict__ bv)
{
    extern __shared__ float sm[];
    float* xs = sm;                 // [32][ROWPAD]
    float* ws = sm + 32 * ROWPAD;   // [K1_COLS][ROWPAD]

    const int nb = Dk / K1_COLS;          // 128 blocks per matrix
    const int mat = blockIdx.x / nb;
    const int colbase = (blockIdx.x % nb) * K1_COLS;

    const float* W; const float* bias; float* out; float scale;
    if (mat == 0)      { W = Wq; bias = bq; out = g_q2; scale = LOG2E; }
    else if (mat == 1) { W = Wk; bias = bk; out = g_k;  scale = 1.0f; }
    else               { W = Wv; bias = bv; out = g_v;  scale = 1.0f; }

    const int tid  = threadIdx.x;
    const int lane = tid & 31;            // lane == batch index
    const int wid  = tid >> 5;            // warp id 0..3

    float acc0 = 0.f, acc1 = 0.f, acc2 = 0.f, acc3 = 0.f;

    for (int chunk = 0; chunk < Dk / 256; chunk++) {
        const int d0 = chunk << 8;
        // load x tile [32][256] coalesced
        for (int idx = tid; idx < 32 * 256; idx += 128) {
            int d = idx & 255, b = idx >> 8;
            xs[b * ROWPAD + d] = x[b * Dk + d0 + d];
        }
        // load W tile [16][256] coalesced
        for (int idx = tid; idx < K1_COLS * 256; idx += 128) {
            int d = idx & 255, c = idx >> 8;
            ws[c * ROWPAD + d] = W[(colbase + c) * Dk + d0 + d];
        }
        __syncthreads();

        const float* xrow = xs + lane * ROWPAD;
        const float* w0 = ws + (wid * 4 + 0) * ROWPAD;
        const float* w1 = ws + (wid * 4 + 1) * ROWPAD;
        const float* w2 = ws + (wid * 4 + 2) * ROWPAD;
        const float* w3 = ws + (wid * 4 + 3) * ROWPAD;

        #pragma unroll 8
        for (int db = 0; db < 256; db += 4) {
            float4 xv  = *(const float4*)(xrow + db);
            float4 wv0 = *(const float4*)(w0 + db);   // broadcast
            float4 wv1 = *(const float4*)(w1 + db);
            float4 wv2 = *(const float4*)(w2 + db);
            float4 wv3 = *(const float4*)(w3 + db);
            acc0 = fmaf(xv.x, wv0.x, acc0); acc0 = fmaf(xv.y, wv0.y, acc0);
            acc0 = fmaf(xv.z, wv0.z, acc0); acc0 = fmaf(xv.w, wv0.w, acc0);
            acc1 = fmaf(xv.x, wv1.x, acc1); acc1 = fmaf(xv.y, wv1.y, acc1);
            acc1 = fmaf(xv.z, wv1.z, acc1); acc1 = fmaf(xv.w, wv1.w, acc1);
            acc2 = fmaf(xv.x, wv2.x, acc2); acc2 = fmaf(xv.y, wv2.y, acc2);
            acc2 = fmaf(xv.z, wv2.z, acc2); acc2 = fmaf(xv.w, wv2.w, acc2);
            acc3 = fmaf(xv.x, wv3.x, acc3); acc3 = fmaf(xv.y, wv3.y, acc3);
            acc3 = fmaf(xv.z, wv3.z, acc3); acc3 = fmaf(xv.w, wv3.w, acc3);
        }
        __syncthreads();
    }

    const int cb = colbase + wid * 4;
    out[lane * Dk + cb + 0] = (acc0 + bias[cb + 0]) * scale;
    out[lane * Dk + cb + 1] = (acc1 + bias[cb + 1]) * scale;
    out[lane * Dk + cb + 2] = (acc2 + bias[cb + 2]) * scale;
    out[lane * Dk + cb + 3] = (acc3 + bias[cb + 3]) * scale;
}

// ---------------------------------------------------------------------------
// K2 (pass1): S_j = sum_i exp2(q2_i*k_j - m2_j),  m2_j = (k_j>0?max:min)*k_j
// Writes packed {k_j, -m2_j, v_j/S_j}. Block: (jchunk of 128, batch).
// ---------------------------------------------------------------------------
__global__ __launch_bounds__(128, 1) void pass1_kernel()
{
    __shared__ float q2s[Dk];                 // 8 KB
    __shared__ float wmx[4], wmn[4];

    const int b   = blockIdx.y;
    const int tid = threadIdx.x;
    const int j   = blockIdx.x * 128 + tid;
    const float* q2 = g_q2 + b * Dk;

    float mx = -CUDART_INF_F, mn = CUDART_INF_F;
    for (int i = tid; i < Dk; i += 128) {
        float v = q2[i];
        q2s[i] = v;
        mx = fmaxf(mx, v); mn = fminf(mn, v);
    }
    #pragma unroll
    for (int o = 16; o; o >>= 1) {
        mx = fmaxf(mx, __shfl_xor_sync(0xffffffffu, mx, o));
        mn = fminf(mn, __shfl_xor_sync(0xffffffffu, mn, o));
    }
    if ((tid & 31) == 0) { wmx[tid >> 5] = mx; wmn[tid >> 5] = mn; }
    __syncthreads();
    mx = fmaxf(fmaxf(wmx[0], wmx[1]), fmaxf(wmx[2], wmx[3]));
    mn = fminf(fminf(wmn[0], wmn[1]), fminf(wmn[2], wmn[3]));

    const float kj    = g_k[b * Dk + j];
    const float negm2 = -((kj > 0.0f) ? mx : mn) * kj;   // exponent = q2*kj + negm2 <= 0

    float a0 = 0.f, a1 = 0.f, a2 = 0.f, a3 = 0.f;
    #pragma unroll 2
    for (int i = 0; i < Dk; i += 4) {
        float4 q = *(const float4*)(q2s + i);            // broadcast LDS.128
        a0 += ex2f(fmaf(q.x, kj, negm2));
        a1 += ex2f(fmaf(q.y, kj, negm2));
        a2 += ex2f(fmaf(q.z, kj, negm2));
        a3 += ex2f(fmaf(q.w, kj, negm2));
    }
    const float S = (a0 + a1) + (a2 + a3);               // >= 1, safe
    const float c = __fdividef(g_v[b * Dk + j], S);
    g_kmc[b * Dk + j] = make_float4(kj, negm2, c, 0.0f);
}

// ---------------------------------------------------------------------------
// K3 (pass2): out[b][i] = sum_j c_j * exp2(q2_i*k_j - m2_j)
// Block: (ichunk of 128, batch). Packed kmc tile in smem (32 KB, broadcast).
// ---------------------------------------------------------------------------
__global__ __launch_bounds__(128, 1) void pass2_kernel(float* __restrict__ out)
{
    __shared__ float4 kmcs[Dk];               // 32 KB
    const int b   = blockIdx.y;
    const int tid = threadIdx.x;
    const int i   = blockIdx.x * 128 + tid;

    const float4* src = g_kmc + b * Dk;
    for (int idx = tid; idx < Dk; idx += 128) kmcs[idx] = src[idx];
    __syncthreads();

    const float qi = g_q2[b * Dk + i];
    float a0 = 0.f, a1 = 0.f, a2 = 0.f, a3 = 0.f;
    #pragma unroll 2
    for (int jj = 0; jj < Dk; jj += 4) {
        float4 p0 = kmcs[jj + 0];
        float4 p1 = kmcs[jj + 1];
        float4 p2 = kmcs[jj + 2];
        float4 p3 = kmcs[jj + 3];
        a0 = fmaf(ex2f(fmaf(qi, p0.x, p0.y)), p0.z, a0);
        a1 = fmaf(ex2f(fmaf(qi, p1.x, p1.y)), p1.z, a1);
        a2 = fmaf(ex2f(fmaf(qi, p2.x, p2.y)), p2.z, a2);
        a3 = fmaf(ex2f(fmaf(qi, p3.x, p3.y)), p3.z, a3);
    }
    out[b * Dk + i] = (a0 + a1) + (a2 + a3);
}

// ---------------------------------------------------------------------------
extern "C" void kernel_launch(void* const* d_in, const int* in_sizes, int n_in,
                              void* d_out, int out_size)
{
    (void)in_sizes; (void)n_in; (void)out_size;
    const float* x  = (const float*)d_in[0];
    const float* Wq = (const float*)d_in[1];
    const float* bq = (const float*)d_in[2];
    const float* Wk = (const float*)d_in[3];
    const float* bk = (const float*)d_in[4];
    const float* Wv = (const float*)d_in[5];
    const float* bv = (const float*)d_in[6];
    float* out = (float*)d_out;

    // Host-side attribute set (not a stream op, not an allocation; idempotent).
    cudaFuncSetAttribute(proj_kernel,
                         cudaFuncAttributeMaxDynamicSharedMemorySize, K1_SMEM);

    proj_kernel<<<3 * (Dk / K1_COLS), 128, K1_SMEM>>>(x, Wq, bq, Wk, bk, Wv, bv);

    dim3 grid_s(Dk / 128, Bk);   // (16, 32)
    pass1_kernel<<<grid_s, 128>>>();
    pass2_kernel<<<grid_s, 128>>>(out);
}

// round 3
// speedup vs baseline: 1.2258x; 1.2258x over previous
#include <cuda_runtime.h>
#include <math_constants.h>

#define Dk 2048
#define Bk 32
#define LOG2E 1.4426950408889634f
#define KSPLIT 8
#define KCHUNK (Dk / KSPLIT)        // 256
#define NCOLS  64                   // cols per block
#define XPAD   68                   // row pad (272B, 16B-aligned, conflict-free)

// Scratch (no allocations allowed) -------------------------------------------
__device__ float  g_part[3 * KSPLIT * Dk * Bk];  // [mat][ks][col][b]  6.3MB
__device__ float  g_q2[Bk * Dk];   // (x@WqT + bq) * log2e
__device__ float  g_k [Bk * Dk];
__device__ float  g_v [Bk * Dk];
__device__ float4 g_kmc[Bk * Dk];  // {k_j, -m2_j, v_j/S_j, 0}

__device__ __forceinline__ float ex2f(float x) {
    float r; asm("ex2.approx.f32 %0, %1;" : "=f"(r) : "f"(x)); return r;
}

// ---------------------------------------------------------------------------
// K1: split-K projection GEMM partials.
// grid.x = 3 mats * 32 colgroups * KSPLIT.  block = 256 thr = 8 warps.
// warp w -> 8 cols, lane -> batch.  Thread: 8 acc chains.
// ---------------------------------------------------------------------------
__global__ __launch_bounds__(256, 1) void proj_kernel(
    const float* __restrict__ x,
    const float* __restrict__ Wq,
    const float* __restrict__ Wk,
    const float* __restrict__ Wv)
{
    __shared__ float xs[32 * XPAD];      // [b][k] tile, K-tile 64
    __shared__ float ws[NCOLS * XPAD];   // [c][k] tile

    const int bx = blockIdx.x;
    const int mat = bx / (32 * KSPLIT);
    const int rem = bx % (32 * KSPLIT);
    const int colbase = (rem / KSPLIT) * NCOLS;
    const int ks  = rem % KSPLIT;
    const int k0base = ks * KCHUNK;

    const float* W = (mat == 0) ? Wq : (mat == 1) ? Wk : Wv;

    const int tid  = threadIdx.x;
    const int lane = tid & 31;           // batch
    const int wid  = tid >> 5;           // warp -> col group of 8

    float acc[8];
    #pragma unroll
    for (int c = 0; c < 8; c++) acc[c] = 0.f;

    for (int s = 0; s < KCHUNK / 64; s++) {
        const int k0 = k0base + s * 64;
        // x tile [32][64]: 512 float4, 2 per thread
        #pragma unroll
        for (int r = 0; r < 2; r++) {
            int idx = r * 256 + tid;           // 0..511
            int b = idx >> 4, kv = idx & 15;
            float4 t = *(const float4*)(x + b * Dk + k0 + kv * 4);
            *(float4*)(xs + b * XPAD + kv * 4) = t;
        }
        // W tile [64][64]: 1024 float4, 4 per thread
        #pragma unroll
        for (int r = 0; r < 4; r++) {
            int idx = r * 256 + tid;           // 0..1023
            int c = idx >> 4, kv = idx & 15;
            float4 t = *(const float4*)(W + (colbase + c) * Dk + k0 + kv * 4);
            *(float4*)(ws + c * XPAD + kv * 4) = t;
        }
        __syncthreads();

        const float* xrow  = xs + lane * XPAD;
        const float* wbase = ws + (wid * 8) * XPAD;

        #pragma unroll 4
        for (int k = 0; k < 64; k += 4) {
            float4 xv = *(const float4*)(xrow + k);
            #pragma unroll
            for (int c = 0; c < 8; c++) {
                float4 wv = *(const float4*)(wbase + c * XPAD + k);  // broadcast
                float a = acc[c];
                a = fmaf(xv.x, wv.x, a);
                a = fmaf(xv.y, wv.y, a);
                a = fmaf(xv.z, wv.z, a);
                a = fmaf(xv.w, wv.w, a);
                acc[c] = a;
            }
        }
        __syncthreads();
    }

    // coalesced: per col, 32 consecutive floats (lane = b)
    float* dst = g_part + (((mat * KSPLIT + ks) * Dk) + colbase + wid * 8) * Bk + lane;
    #pragma unroll
    for (int c = 0; c < 8; c++) dst[c * Bk] = acc[c];
}

// ---------------------------------------------------------------------------
// K1b: reduce over KSPLIT + bias + scale + transpose [col][b] -> [b][col].
// grid.x = 3 * 32, block 256.  Tile: 64 cols x 32 b.
// ---------------------------------------------------------------------------
__global__ __launch_bounds__(256, 1) void reduce_kernel(
    const float* __restrict__ bq,
    const float* __restrict__ bk,
    const float* __restrict__ bv)
{
    __shared__ float s[NCOLS][33];

    const int mat = blockIdx.x / 32;
    const int colbase = (blockIdx.x % 32) * NCOLS;
    const int tid = threadIdx.x;

    const float* bias; float* out; float scale;
    if (mat == 0)      { bias = bq; out = g_q2; scale = LOG2E; }
    else if (mat == 1) { bias = bk; out = g_k;  scale = 1.0f; }
    else               { bias = bv; out = g_v;  scale = 1.0f; }

    const float* src = g_part + (mat * KSPLIT * Dk + colbase) * Bk;

    // read phase: consecutive tid -> consecutive b (coalesced)
    #pragma unroll
    for (int it = 0; it < 8; it++) {
        int e = it * 256 + tid;          // 0..2047
        int c = e >> 5, b = e & 31;
        float sum = 0.f;
        #pragma unroll
        for (int p = 0; p < KSPLIT; p++)
            sum += src[p * Dk * Bk + c * Bk + b];
        s[c][b] = sum;
    }
    __syncthreads();

    // write phase: consecutive tid -> consecutive col (coalesced)
    #pragma unroll
    for (int it = 0; it < 8; it++) {
        int e = it * 256 + tid;
        int b = e >> 6, c = e & 63;
        out[b * Dk + colbase + c] = (s[c][b] + bias[colbase + c]) * scale;
    }
}

// ---------------------------------------------------------------------------
// K2 (pass1): S_j = sum_i exp2(q2_i*k_j - m2_j),  m2_j = (k_j>0?max:min)*k_j
// Writes packed {k_j, -m2_j, v_j/S_j}. Block: (jchunk of 128, batch).
// ---------------------------------------------------------------------------
__global__ __launch_bounds__(128, 1) void pass1_kernel()
{
    __shared__ float q2s[Dk];                 // 8 KB
    __shared__ float wmx[4], wmn[4];

    const int b   = blockIdx.y;
    const int tid = threadIdx.x;
    const int j   = blockIdx.x * 128 + tid;
    const float* q2 = g_q2 + b * Dk;

    float mx = -CUDART_INF_F, mn = CUDART_INF_F;
    for (int i = tid; i < Dk; i += 128) {
        float v = q2[i];
        q2s[i] = v;
        mx = fmaxf(mx, v); mn = fminf(mn, v);
    }
    #pragma unroll
    for (int o = 16; o; o >>= 1) {
        mx = fmaxf(mx, __shfl_xor_sync(0xffffffffu, mx, o));
        mn = fminf(mn, __shfl_xor_sync(0xffffffffu, mn, o));
    }
    if ((tid & 31) == 0) { wmx[tid >> 5] = mx; wmn[tid >> 5] = mn; }
    __syncthreads();
    mx = fmaxf(fmaxf(wmx[0], wmx[1]), fmaxf(wmx[2], wmx[3]));
    mn = fminf(fminf(wmn[0], wmn[1]), fminf(wmn[2], wmn[3]));

    const float kj    = g_k[b * Dk + j];
    const float negm2 = -((kj > 0.0f) ? mx : mn) * kj;   // exponent <= 0

    float a0 = 0.f, a1 = 0.f, a2 = 0.f, a3 = 0.f;
    #pragma unroll 2
    for (int i = 0; i < Dk; i += 4) {
        float4 q = *(const float4*)(q2s + i);            // broadcast LDS.128
        a0 += ex2f(fmaf(q.x, kj, negm2));
        a1 += ex2f(fmaf(q.y, kj, negm2));
        a2 += ex2f(fmaf(q.z, kj, negm2));
        a3 += ex2f(fmaf(q.w, kj, negm2));
    }
    const float S = (a0 + a1) + (a2 + a3);               // >= 1, safe
    const float c = __fdividef(g_v[b * Dk + j], S);
    g_kmc[b * Dk + j] = make_float4(kj, negm2, c, 0.0f);
}

// ---------------------------------------------------------------------------
// K3 (pass2): out[b][i] = sum_j c_j * exp2(q2_i*k_j - m2_j)
// ---------------------------------------------------------------------------
__global__ __launch_bounds__(128, 1) void pass2_kernel(float* __restrict__ out)
{
    __shared__ float4 kmcs[Dk];               // 32 KB
    const int b   = blockIdx.y;
    const int tid = threadIdx.x;
    const int i   = blockIdx.x * 128 + tid;

    const float4* src = g_kmc + b * Dk;
    for (int idx = tid; idx < Dk; idx += 128) kmcs[idx] = src[idx];
    __syncthreads();

    const float qi = g_q2[b * Dk + i];
    float a0 = 0.f, a1 = 0.f, a2 = 0.f, a3 = 0.f;
    #pragma unroll 2
    for (int jj = 0; jj < Dk; jj += 4) {
        float4 p0 = kmcs[jj + 0];
        float4 p1 = kmcs[jj + 1];
        float4 p2 = kmcs[jj + 2];
        float4 p3 = kmcs[jj + 3];
        a0 = fmaf(ex2f(fmaf(qi, p0.x, p0.y)), p0.z, a0);
        a1 = fmaf(ex2f(fmaf(qi, p1.x, p1.y)), p1.z, a1);
        a2 = fmaf(ex2f(fmaf(qi, p2.x, p2.y)), p2.z, a2);
        a3 = fmaf(ex2f(fmaf(qi, p3.x, p3.y)), p3.z, a3);
    }
    out[b * Dk + i] = (a0 + a1) + (a2 + a3);
}

// ---------------------------------------------------------------------------
extern "C" void kernel_launch(void* const* d_in, const int* in_sizes, int n_in,
                              void* d_out, int out_size)
{
    (void)in_sizes; (void)n_in; (void)out_size;
    const float* x  = (const float*)d_in[0];
    const float* Wq = (const float*)d_in[1];
    const float* bq = (const float*)d_in[2];
    const float* Wk = (const float*)d_in[3];
    const float* bk = (const float*)d_in[4];
    const float* Wv = (const float*)d_in[5];
    const float* bv = (const float*)d_in[6];
    float* out = (float*)d_out;

    proj_kernel<<<3 * 32 * KSPLIT, 256>>>(x, Wq, Wk, Wv);
    reduce_kernel<<<3 * 32, 256>>>(bq, bk, bv);

    dim3 grid_s(Dk / 128, Bk);   // (16, 32)
    pass1_kernel<<<grid_s, 128>>>();
    pass2_kernel<<<grid_s, 128>>>(out);
}